// round 16
// baseline (speedup 1.0000x reference)
#include <cuda_runtime.h>
#include <cuda_fp16.h>
#include <cuda_bf16.h>
#include <cstdint>

#define BB 8
#define TT 2048
#define CC 1024
#define MM (BB*TT)          // 16384 rows

// ---------------- scratch (static device arrays; no allocation) -------------
__device__ __half g_kvr[(size_t)MM * 3 * CC];    // k,v,r fp16 (traffic win)
__device__ float g_x1 [(size_t)MM * CC];
__device__ float g_rr [(size_t)MM * CC];
__device__ __half g_xn  [(size_t)MM * CC];
__device__ __half g_xn2 [(size_t)MM * CC];
__device__ __half g_hid [(size_t)MM * 4 * CC];
__device__ __half g_wtm [(size_t)3 * CC * CC];   // W_tm^T  [3C, C]
__device__ __half g_wcm [(size_t)4 * CC * CC];   // W_cm^T  [4C, C]
__device__ __half g_wcp [(size_t)CC * 4 * CC];   // W_cp^T  [C, 4C]

__device__ __forceinline__ float sigmoidf_(float z) {
    return 1.0f / (1.0f + __expf(-z));
}
__device__ __forceinline__ uint32_t smem_u32(const void* p) {
    uint32_t a;
    asm("{ .reg .u64 t; cvta.to.shared.u64 t, %1; cvt.u32.u64 %0, t; }"
        : "=r"(a) : "l"(p));
    return a;
}
__device__ __forceinline__ void cp16(uint32_t sa, const void* ga) {
    asm volatile("cp.async.cg.shared.global [%0], [%1], 16;"
                 :: "r"(sa), "l"(ga) : "memory");
}
__device__ __forceinline__ void cp_commit() {
    asm volatile("cp.async.commit_group;" ::: "memory");
}
__device__ __forceinline__ void ldx4(uint32_t* r, uint32_t addr) {
    asm volatile("ldmatrix.sync.aligned.m8n8.x4.shared.b16 {%0,%1,%2,%3}, [%4];"
                 : "=r"(r[0]), "=r"(r[1]), "=r"(r[2]), "=r"(r[3]) : "r"(addr));
}
__device__ __forceinline__ void mma16816(float* c, const uint32_t* a,
                                         uint32_t b0, uint32_t b1) {
    asm volatile(
        "mma.sync.aligned.m16n8k16.row.col.f32.f16.f16.f32 "
        "{%0,%1,%2,%3}, {%4,%5,%6,%7}, {%8,%9}, {%0,%1,%2,%3};"
        : "+f"(c[0]), "+f"(c[1]), "+f"(c[2]), "+f"(c[3])
        : "r"(a[0]), "r"(a[1]), "r"(a[2]), "r"(a[3]), "r"(b0), "r"(b1));
}

// ---------------- weight transpose -> fp16 -----------------------------------
__global__ void transpose_h(const float* __restrict__ W,
                            __half* __restrict__ Th, int K, int N) {
    __shared__ float tile[32][33];
    int n0 = blockIdx.x * 32, k0 = blockIdx.y * 32;
    int tx = threadIdx.x, ty = threadIdx.y;  // 32 x 8
    #pragma unroll
    for (int i = 0; i < 32; i += 8)
        tile[ty + i][tx] = W[(size_t)(k0 + ty + i) * N + n0 + tx];
    __syncthreads();
    #pragma unroll
    for (int i = 0; i < 32; i += 8)
        Th[(size_t)(n0 + ty + i) * K + k0 + tx] = __float2half_rn(tile[tx][ty + i]);
}

// ---------------- LayerNorm 1 -> fp16 ----------------------------------------
__global__ void ln1_kernel(const float* __restrict__ x,
                           const float* __restrict__ g,
                           const float* __restrict__ b,
                           __half* __restrict__ oh) {
    int row = blockIdx.x;
    float4 v = ((const float4*)(x + (size_t)row * CC))[threadIdx.x];
    float s = v.x + v.y + v.z + v.w;
    float q = v.x*v.x + v.y*v.y + v.z*v.z + v.w*v.w;
    int lane = threadIdx.x & 31, wid = threadIdx.x >> 5;
    #pragma unroll
    for (int o = 16; o; o >>= 1) {
        s += __shfl_xor_sync(0xffffffffu, s, o);
        q += __shfl_xor_sync(0xffffffffu, q, o);
    }
    __shared__ float s_s[8], s_q[8];
    if (!lane) { s_s[wid] = s; s_q[wid] = q; }
    __syncthreads();
    if (threadIdx.x == 0) {
        float a = 0.f, c2 = 0.f;
        #pragma unroll
        for (int i = 0; i < 8; i++) { a += s_s[i]; c2 += s_q[i]; }
        s_s[0] = a; s_q[0] = c2;
    }
    __syncthreads();
    float mean = s_s[0] * (1.0f / CC);
    float var  = s_q[0] * (1.0f / CC) - mean * mean;
    float rstd = rsqrtf(var + 1e-5f);
    float4 gv = ((const float4*)g)[threadIdx.x];
    float4 bv = ((const float4*)b)[threadIdx.x];
    __half2 h01 = __floats2half2_rn((v.x - mean) * rstd * gv.x + bv.x,
                                    (v.y - mean) * rstd * gv.y + bv.y);
    __half2 h23 = __floats2half2_rn((v.z - mean) * rstd * gv.z + bv.z,
                                    (v.w - mean) * rstd * gv.w + bv.w);
    __half2* ph = (__half2*)(oh + (size_t)row * CC);
    ph[threadIdx.x * 2] = h01;  ph[threadIdx.x * 2 + 1] = h23;
}

// ---------------- LayerNorm 2 + rr gate -> fp16 ------------------------------
__global__ void ln2_rr_kernel(const float* __restrict__ x1,
                              const float* __restrict__ g,
                              const float* __restrict__ b,
                              const float* __restrict__ cmr,
                              __half* __restrict__ oh,
                              float* __restrict__ rr) {
    int row = blockIdx.x;
    float4 v = ((const float4*)(x1 + (size_t)row * CC))[threadIdx.x];
    float s = v.x + v.y + v.z + v.w;
    float q = v.x*v.x + v.y*v.y + v.z*v.z + v.w*v.w;
    int lane = threadIdx.x & 31, wid = threadIdx.x >> 5;
    #pragma unroll
    for (int o = 16; o; o >>= 1) {
        s += __shfl_xor_sync(0xffffffffu, s, o);
        q += __shfl_xor_sync(0xffffffffu, q, o);
    }
    __shared__ float s_s[8], s_q[8];
    if (!lane) { s_s[wid] = s; s_q[wid] = q; }
    __syncthreads();
    if (threadIdx.x == 0) {
        float a = 0.f, c2 = 0.f;
        #pragma unroll
        for (int i = 0; i < 8; i++) { a += s_s[i]; c2 += s_q[i]; }
        s_s[0] = a; s_q[0] = c2;
    }
    __syncthreads();
    float mean = s_s[0] * (1.0f / CC);
    float var  = s_q[0] * (1.0f / CC) - mean * mean;
    float rstd = rsqrtf(var + 1e-5f);
    float4 gv = ((const float4*)g)[threadIdx.x];
    float4 bv = ((const float4*)b)[threadIdx.x];
    float o0 = (v.x - mean) * rstd * gv.x + bv.x;
    float o1 = (v.y - mean) * rstd * gv.y + bv.y;
    float o2 = (v.z - mean) * rstd * gv.z + bv.z;
    float o3 = (v.w - mean) * rstd * gv.w + bv.w;
    __half2* ph = (__half2*)(oh + (size_t)row * CC);
    ph[threadIdx.x * 2]     = __floats2half2_rn(o0, o1);
    ph[threadIdx.x * 2 + 1] = __floats2half2_rn(o2, o3);

    int t = row & (TT - 1);
    int prow = (t == 0) ? (row + TT - 1) : (row - 1);
    float4 xp = ((const float4*)(x1 + (size_t)prow * CC))[threadIdx.x];
    float4 cr = ((const float4*)cmr)[threadIdx.x];
    float4 r4;
    r4.x = sigmoidf_(xp.x + cr.x * (o0 - xp.x));
    r4.y = sigmoidf_(xp.y + cr.y * (o1 - xp.y));
    r4.z = sigmoidf_(xp.z + cr.z * (o2 - xp.z));
    r4.w = sigmoidf_(xp.w + cr.w * (o3 - xp.w));
    ((float4*)(rr + (size_t)row * CC))[threadIdx.x] = r4;
}

// ---------------- WKV scan (fused x1 = x + r*y), fp16 kvr --------------------
#define PF 8
__global__ void wkv_kernel(const __half* __restrict__ kvr,
                           const float* __restrict__ x,
                           const float* __restrict__ wd,
                           const float* __restrict__ uf,
                           float* __restrict__ x1,
                           float* __restrict__ out_state) {
    int gid = blockIdx.x * blockDim.x + threadIdx.x;
    int b = gid >> 10, c = gid & (CC - 1);
    float w = wd[c], u = uf[c];
    float aa = 0.0f, bb = -1e38f;
    size_t kbase = (size_t)b * TT * (3 * CC) + c;
    size_t xbase = (size_t)b * TT * CC + c;

    float pk[PF], pv[PF], pr[PF], px[PF];
    #pragma unroll
    for (int i = 0; i < PF; i++) {
        size_t ko = kbase + (size_t)i * (3 * CC);
        pk[i] = __half2float(kvr[ko]);
        pv[i] = __half2float(kvr[ko + CC]);
        pr[i] = __half2float(kvr[ko + 2 * CC]);
        px[i] = x[xbase + (size_t)i * CC];
    }
    for (int t0 = 0; t0 < TT; t0 += PF) {
        #pragma unroll
        for (int i = 0; i < PF; i++) {
            int t = t0 + i;
            float kk = pk[i], vv = pv[i], r = pr[i], xv = px[i];
            int tn = t + PF;
            if (tn < TT) {
                size_t ko = kbase + (size_t)tn * (3 * CC);
                pk[i] = __half2float(kvr[ko]);
                pv[i] = __half2float(kvr[ko + CC]);
                pr[i] = __half2float(kvr[ko + 2 * CC]);
                px[i] = x[xbase + (size_t)tn * CC];
            }
            float ww = u + kk;
            float p  = fmaxf(bb, ww);
            float e1 = __expf(bb - p);
            float e2 = __expf(ww - p);
            float y  = __fdividef(e1 * aa + e2 * vv, e1 + e2 + 1e-8f);
            x1[xbase + (size_t)t * CC] = xv + r * y;
            float w2 = w + bb;
            float p2 = fmaxf(w2, kk);
            float ea = __expf(w2 - p2);
            float eb = __expf(kk - p2);
            aa = ea * aa + eb * vv;
            bb = p2 + __logf(ea + eb + 1e-8f);
        }
    }
    out_state[(size_t)gid * 2 + 0] = aa;
    out_state[(size_t)gid * 2 + 1] = bb;
}

// ---------------- HMMA GEMM (G1/G2): C[128,256], warp 64x64 ------------------
#define BKG 64
#define STAGES 3
#define STG_BYTES 49152            // A 128x64x2 = 16KB | B 256x64x2 = 32KB
#define GSMEM (STAGES * STG_BYTES)

template <int EPI>
__global__ void __launch_bounds__(256, 1)
mma_gemm(const __half* __restrict__ A, const __half* __restrict__ B,
         int K,
         __half* __restrict__ outh,
         const float* __restrict__ e0, const float* __restrict__ e1,
         const float* __restrict__ e2, const float* __restrict__ e3) {
    extern __shared__ char smem[];
    const int tid = threadIdx.x;
    const int m0 = blockIdx.y * 128;
    const int n0 = blockIdx.x * 256;
    uint32_t sb = smem_u32(smem);
    const int warp = tid >> 5, lane = tid & 31;
    const int wm = warp >> 2, wn = warp & 3;   // warp tile: 64(m) x 64(n)

    float acc[4][8][4];
    #pragma unroll
    for (int i = 0; i < 4; i++)
        #pragma unroll
        for (int j = 0; j < 8; j++)
            #pragma unroll
            for (int e = 0; e < 4; e++) acc[i][j][e] = 0.f;

    const __half* Ab = A + (size_t)m0 * K;
    const __half* Bb = B + (size_t)n0 * K;
    const int crow = tid >> 3;            // 0..31
    const int ccol = tid & 7;             // 16B chunk 0..7

    auto copy_stage = [&](int ks, int buf) {
        int k0 = ks * BKG;
        uint32_t base = sb + (uint32_t)buf * STG_BYTES;
        #pragma unroll
        for (int i = 0; i < 4; i++) {     // A: 128 rows
            int row = i * 32 + crow;
            uint32_t sa = base + (uint32_t)row * 128 + (uint32_t)((ccol ^ (row & 7)) << 4);
            cp16(sa, Ab + (size_t)row * K + k0 + ccol * 8);
        }
        #pragma unroll
        for (int i = 0; i < 8; i++) {     // B: 256 rows
            int row = i * 32 + crow;
            uint32_t sa = base + 16384 + (uint32_t)row * 128 + (uint32_t)((ccol ^ (row & 7)) << 4);
            cp16(sa, Bb + (size_t)row * K + k0 + ccol * 8);
        }
        cp_commit();
    };

    copy_stage(0, 0);
    copy_stage(1, 1);

    const int lhalf = (lane >> 4) << 4;
    uint32_t a_base[4], a_sw[4], b_base[4], b_sw[4];
    #pragma unroll
    for (int mi = 0; mi < 4; mi++) {
        int row = wm * 64 + mi * 16 + (lane & 15);
        a_base[mi] = (uint32_t)row * 128;
        a_sw[mi]   = (uint32_t)((row & 7) << 4);
    }
    #pragma unroll
    for (int nq = 0; nq < 4; nq++) {
        int row = wn * 64 + nq * 16 + (lane & 15);
        b_base[nq] = 16384u + (uint32_t)row * 128;
        b_sw[nq]   = (uint32_t)((row & 7) << 4);
    }

    uint32_t afr[2][4][4];
    uint32_t bfr[2][4][4];

    auto load_frags = [&](uint32_t bufb, int kk, int fb) {
        uint32_t ch = (uint32_t)(kk * 32 + lhalf);
        #pragma unroll
        for (int mi = 0; mi < 4; mi++)
            ldx4(afr[fb][mi], bufb + a_base[mi] + (ch ^ a_sw[mi]));
        #pragma unroll
        for (int nq = 0; nq < 4; nq++)
            ldx4(bfr[fb][nq], bufb + b_base[nq] + (ch ^ b_sw[nq]));
    };
    auto do_mmas = [&](int fb) {
        #pragma unroll
        for (int mi = 0; mi < 4; mi++)
            #pragma unroll
            for (int nq = 0; nq < 4; nq++) {
                mma16816(acc[mi][2*nq+0], afr[fb][mi], bfr[fb][nq][0], bfr[fb][nq][2]);
                mma16816(acc[mi][2*nq+1], afr[fb][mi], bfr[fb][nq][1], bfr[fb][nq][3]);
            }
    };

    const int NK = K / BKG;
    asm volatile("cp.async.wait_group 1;" ::: "memory");
    __syncthreads();
    load_frags(sb, 0, 0);

    for (int ks = 0; ks < NK; ks++) {
        uint32_t bufb = sb + (uint32_t)(ks % STAGES) * STG_BYTES;
        #pragma unroll
        for (int kk = 0; kk < 4; kk++) {
            if (kk < 3) {
                load_frags(bufb, kk + 1, (kk + 1) & 1);
            } else if (ks + 1 < NK) {
                __syncthreads();
                if (ks + 2 < NK) copy_stage(ks + 2, (ks + 2) % STAGES);
                else cp_commit();
                asm volatile("cp.async.wait_group 1;" ::: "memory");
                __syncthreads();
                load_frags(sb + (uint32_t)((ks + 1) % STAGES) * STG_BYTES, 0, 0);
            }
            do_mmas(kk & 1);
        }
    }

    const int qr = lane >> 2;
    const int qe = lane & 3;
    #pragma unroll
    for (int mi = 0; mi < 4; mi++) {
        #pragma unroll
        for (int rh = 0; rh < 2; rh++) {
            int m = m0 + wm * 64 + mi * 16 + qr + rh * 8;
            int t = m & (TT - 1);
            if (EPI == 1) {
                int seg = n0 >> 10;
                const float* coefp = (seg == 0) ? e1 : (seg == 1) ? e2 : e3;
                int pm = t ? (m - 1) : m;
                const float* xpr = e0 + (size_t)pm * CC;
                __half* orow = outh + (size_t)m * (3 * CC);
                #pragma unroll
                for (int nj = 0; nj < 8; nj++) {
                    int n = n0 + wn * 64 + nj * 8 + 2 * qe;
                    int c = n & (CC - 1);
                    float v0 = acc[mi][nj][rh * 2 + 0];
                    float v1 = acc[mi][nj][rh * 2 + 1];
                    float x0 = xpr[c], x1v = xpr[c + 1];
                    float a0 = x0  + coefp[c]     * (v0 - x0);
                    float a1 = x1v + coefp[c + 1] * (v1 - x1v);
                    if (seg == 2) { a0 = sigmoidf_(a0); a1 = sigmoidf_(a1); }
                    *(__half2*)(orow + n) = __floats2half2_rn(a0, a1);
                }
            } else {       // EPI == 2
                int pm = t ? (m - 1) : (m + TT - 1);
                const float* xpr = e0 + (size_t)pm * CC;
                size_t rowo = (size_t)m * (4 * CC);
                #pragma unroll
                for (int nj = 0; nj < 8; nj++) {
                    int n = n0 + wn * 64 + nj * 8 + 2 * qe;
                    int c = n & (CC - 1);
                    float v0 = acc[mi][nj][rh * 2 + 0];
                    float v1 = acc[mi][nj][rh * 2 + 1];
                    float x0 = xpr[c], x1v = xpr[c + 1];
                    float a0 = fmaxf(x0  + e1[c]     * (v0 - x0), 0.f);
                    float a1 = fmaxf(x1v + e1[c + 1] * (v1 - x1v), 0.f);
                    *(__half2*)(outh + rowo + n) = __floats2half2_rn(a0 * a0, a1 * a1);
                }
            }
        }
    }
}

// ---------------- HMMA GEMM3: C[128,128], warp 64x32 -------------------------
#define STG3_BYTES 32768           // A 128x64x2 = 16KB | B 128x64x2 = 16KB
#define G3SMEM (STAGES * STG3_BYTES)

__global__ void __launch_bounds__(256, 1)
mma_gemm3(const __half* __restrict__ A, const __half* __restrict__ B,
          int K, float* __restrict__ outf,
          const float* __restrict__ e0, const float* __restrict__ e1) {
    extern __shared__ char smem[];
    const int tid = threadIdx.x;
    const int m0 = blockIdx.y * 128;
    const int n0 = blockIdx.x * 128;
    uint32_t sb = smem_u32(smem);
    const int warp = tid >> 5, lane = tid & 31;
    const int wm = warp >> 2, wn = warp & 3;   // warp tile: 64(m) x 32(n)

    float acc[4][4][4];
    #pragma unroll
    for (int i = 0; i < 4; i++)
        #pragma unroll
        for (int j = 0; j < 4; j++)
            #pragma unroll
            for (int e = 0; e < 4; e++) acc[i][j][e] = 0.f;

    const __half* Ab = A + (size_t)m0 * K;
    const __half* Bb = B + (size_t)n0 * K;
    const int crow = tid >> 3;
    const int ccol = tid & 7;

    auto copy_stage = [&](int ks, int buf) {
        int k0 = ks * BKG;
        uint32_t base = sb + (uint32_t)buf * STG3_BYTES;
        #pragma unroll
        for (int i = 0; i < 4; i++) {     // A: 128 rows
            int row = i * 32 + crow;
            uint32_t sa = base + (uint32_t)row * 128 + (uint32_t)((ccol ^ (row & 7)) << 4);
            cp16(sa, Ab + (size_t)row * K + k0 + ccol * 8);
        }
        #pragma unroll
        for (int i = 0; i < 4; i++) {     // B: 128 rows
            int row = i * 32 + crow;
            uint32_t sa = base + 16384 + (uint32_t)row * 128 + (uint32_t)((ccol ^ (row & 7)) << 4);
            cp16(sa, Bb + (size_t)row * K + k0 + ccol * 8);
        }
        cp_commit();
    };

    copy_stage(0, 0);
    copy_stage(1, 1);

    const int lhalf = (lane >> 4) << 4;
    uint32_t a_base[4], a_sw[4], b_base[2], b_sw[2];
    #pragma unroll
    for (int mi = 0; mi < 4; mi++) {
        int row = wm * 64 + mi * 16 + (lane & 15);
        a_base[mi] = (uint32_t)row * 128;
        a_sw[mi]   = (uint32_t)((row & 7) << 4);
    }
    #pragma unroll
    for (int nq = 0; nq < 2; nq++) {
        int row = wn * 32 + nq * 16 + (lane & 15);
        b_base[nq] = 16384u + (uint32_t)row * 128;
        b_sw[nq]   = (uint32_t)((row & 7) << 4);
    }

    uint32_t afr[2][4][4];
    uint32_t bfr[2][2][4];

    auto load_frags = [&](uint32_t bufb, int kk, int fb) {
        uint32_t ch = (uint32_t)(kk * 32 + lhalf);
        #pragma unroll
        for (int mi = 0; mi < 4; mi++)
            ldx4(afr[fb][mi], bufb + a_base[mi] + (ch ^ a_sw[mi]));
        #pragma unroll
        for (int nq = 0; nq < 2; nq++)
            ldx4(bfr[fb][nq], bufb + b_base[nq] + (ch ^ b_sw[nq]));
    };
    auto do_mmas = [&](int fb) {
        #pragma unroll
        for (int mi = 0; mi < 4; mi++)
            #pragma unroll
            for (int nq = 0; nq < 2; nq++) {
                mma16816(acc[mi][2*nq+0], afr[fb][mi], bfr[fb][nq][0], bfr[fb][nq][2]);
                mma16816(acc[mi][2*nq+1], afr[fb][mi], bfr[fb][nq][1], bfr[fb][nq][3]);
            }
    };

    const int NK = K / BKG;
    asm volatile("cp.async.wait_group 1;" ::: "memory");
    __syncthreads();
    load_frags(sb, 0, 0);

    for (int ks = 0; ks < NK; ks++) {
        uint32_t bufb = sb + (uint32_t)(ks % STAGES) * STG3_BYTES;
        #pragma unroll
        for (int kk = 0; kk < 4; kk++) {
            if (kk < 3) {
                load_frags(bufb, kk + 1, (kk + 1) & 1);
            } else if (ks + 1 < NK) {
                __syncthreads();
                if (ks + 2 < NK) copy_stage(ks + 2, (ks + 2) % STAGES);
                else cp_commit();
                asm volatile("cp.async.wait_group 1;" ::: "memory");
                __syncthreads();
                load_frags(sb + (uint32_t)((ks + 1) % STAGES) * STG3_BYTES, 0, 0);
            }
            do_mmas(kk & 1);
        }
    }

    const int qr = lane >> 2;
    const int qe = lane & 3;
    #pragma unroll
    for (int mi = 0; mi < 4; mi++) {
        #pragma unroll
        for (int rh = 0; rh < 2; rh++) {
            int m = m0 + wm * 64 + mi * 16 + qr + rh * 8;
            size_t rowo = (size_t)m * CC;
            #pragma unroll
            for (int nj = 0; nj < 4; nj++) {
                int n = n0 + wn * 32 + nj * 8 + 2 * qe;
                float2 xv = *(const float2*)(e0 + rowo + n);
                float2 rv = *(const float2*)(e1 + rowo + n);
                float2 o;
                o.x = xv.x + rv.x * acc[mi][nj][rh * 2 + 0];
                o.y = xv.y + rv.y * acc[mi][nj][rh * 2 + 1];
                *(float2*)(outf + rowo + n) = o;
            }
        }
    }
}

// ---------------- launch ------------------------------------------------------
extern "C" void kernel_launch(void* const* d_in, const int* in_sizes, int n_in,
                              void* d_out, int out_size) {
    const float* x    = (const float*)d_in[0];
    const float* tdec = (const float*)d_in[1];
    const float* tfir = (const float*)d_in[2];
    const float* W_tm = (const float*)d_in[3];
    const float* g1   = (const float*)d_in[4];
    const float* b1   = (const float*)d_in[5];
    const float* tmk  = (const float*)d_in[6];
    const float* tmv  = (const float*)d_in[7];
    const float* tmr  = (const float*)d_in[8];
    const float* W_cm = (const float*)d_in[9];
    const float* W_cp = (const float*)d_in[10];
    const float* g2   = (const float*)d_in[11];
    const float* b2   = (const float*)d_in[12];
    const float* cmk  = (const float*)d_in[13];
    const float* cmr  = (const float*)d_in[14];
    float* out = (float*)d_out;

    float *x1, *rr;
    __half *kvr, *xn, *xn2, *hid, *wtm, *wcm, *wcp;
    cudaGetSymbolAddress((void**)&kvr, g_kvr);
    cudaGetSymbolAddress((void**)&x1,  g_x1);
    cudaGetSymbolAddress((void**)&rr,  g_rr);
    cudaGetSymbolAddress((void**)&xn,  g_xn);
    cudaGetSymbolAddress((void**)&xn2, g_xn2);
    cudaGetSymbolAddress((void**)&hid, g_hid);
    cudaGetSymbolAddress((void**)&wtm, g_wtm);
    cudaGetSymbolAddress((void**)&wcm, g_wcm);
    cudaGetSymbolAddress((void**)&wcp, g_wcp);

    cudaFuncSetAttribute(mma_gemm<1>, cudaFuncAttributeMaxDynamicSharedMemorySize, GSMEM);
    cudaFuncSetAttribute(mma_gemm<2>, cudaFuncAttributeMaxDynamicSharedMemorySize, GSMEM);
    cudaFuncSetAttribute(mma_gemm3,   cudaFuncAttributeMaxDynamicSharedMemorySize, G3SMEM);

    dim3 tb(32, 8);
    transpose_h<<<dim3(3*CC/32, CC/32), tb>>>(W_tm, wtm, CC, 3*CC);
    transpose_h<<<dim3(4*CC/32, CC/32), tb>>>(W_cm, wcm, CC, 4*CC);
    transpose_h<<<dim3(CC/32, 4*CC/32), tb>>>(W_cp, wcp, 4*CC, CC);

    // 1) LN1 -> fp16
    ln1_kernel<<<MM, 256>>>(x, g1, b1, xn);
    // 2) GEMM1 + time-mix epilogue -> kvr (fp16)
    mma_gemm<1><<<dim3(3*CC/256, MM/128), 256, GSMEM>>>(
        xn, wtm, CC, kvr, x, tmk, tmv, tmr);
    // 3) WKV scan (fp16 kvr) -> x1 (fp32), state tail of out
    wkv_kernel<<<(BB*CC)/64, 64>>>(kvr, x, tdec, tfir, x1, out + (size_t)MM * CC);
    // 4) LN2 + rr gate -> fp16 + rr
    ln2_rr_kernel<<<MM, 256>>>(x1, g2, b2, cmr, xn2, rr);
    // 5) GEMM2 + channel-mix relu^2 epilogue -> hidden fp16
    mma_gemm<2><<<dim3(4*CC/256, MM/128), 256, GSMEM>>>(
        xn2, wcm, CC, hid, x1, cmk, nullptr, nullptr);
    // 6) GEMM3 (128x128 tiles) + final epilogue -> out = x1 + rr*vv
    mma_gemm3<<<dim3(CC/128, MM/128), 256, G3SMEM>>>(
        hid, wcp, 4*CC, out, x1, rr);
}

// round 17
// speedup vs baseline: 1.5971x; 1.5971x over previous
#include <cuda_runtime.h>
#include <cuda_fp16.h>
#include <cuda_bf16.h>
#include <cstdint>

#define BB 8
#define TT 2048
#define CC 1024
#define MM (BB*TT)          // 16384 rows

// ---------------- scratch (static device arrays; no allocation) -------------
__device__ float g_kvr[(size_t)MM * 3 * CC];     // fp32: k feeds exp() — fp16 fails
__device__ float g_x1 [(size_t)MM * CC];
__device__ float g_rr [(size_t)MM * CC];
__device__ __half g_xn  [(size_t)MM * CC];
__device__ __half g_xn2 [(size_t)MM * CC];
__device__ __half g_hid [(size_t)MM * 4 * CC];
__device__ __half g_wtm [(size_t)3 * CC * CC];   // W_tm^T  [3C, C]
__device__ __half g_wcm [(size_t)4 * CC * CC];   // W_cm^T  [4C, C]
__device__ __half g_wcp [(size_t)CC * 4 * CC];   // W_cp^T  [C, 4C]

__device__ __forceinline__ float sigmoidf_(float z) {
    return 1.0f / (1.0f + __expf(-z));
}
__device__ __forceinline__ uint32_t smem_u32(const void* p) {
    uint32_t a;
    asm("{ .reg .u64 t; cvta.to.shared.u64 t, %1; cvt.u32.u64 %0, t; }"
        : "=r"(a) : "l"(p));
    return a;
}
__device__ __forceinline__ void cp16(uint32_t sa, const void* ga) {
    asm volatile("cp.async.cg.shared.global [%0], [%1], 16;"
                 :: "r"(sa), "l"(ga) : "memory");
}
__device__ __forceinline__ void cp_commit() {
    asm volatile("cp.async.commit_group;" ::: "memory");
}
__device__ __forceinline__ void ldx4(uint32_t* r, uint32_t addr) {
    asm volatile("ldmatrix.sync.aligned.m8n8.x4.shared.b16 {%0,%1,%2,%3}, [%4];"
                 : "=r"(r[0]), "=r"(r[1]), "=r"(r[2]), "=r"(r[3]) : "r"(addr));
}
__device__ __forceinline__ void mma16816(float* c, const uint32_t* a,
                                         uint32_t b0, uint32_t b1) {
    asm volatile(
        "mma.sync.aligned.m16n8k16.row.col.f32.f16.f16.f32 "
        "{%0,%1,%2,%3}, {%4,%5,%6,%7}, {%8,%9}, {%0,%1,%2,%3};"
        : "+f"(c[0]), "+f"(c[1]), "+f"(c[2]), "+f"(c[3])
        : "r"(a[0]), "r"(a[1]), "r"(a[2]), "r"(a[3]), "r"(b0), "r"(b1));
}

// ---------------- weight transpose -> fp16 -----------------------------------
__global__ void transpose_h(const float* __restrict__ W,
                            __half* __restrict__ Th, int K, int N) {
    __shared__ float tile[32][33];
    int n0 = blockIdx.x * 32, k0 = blockIdx.y * 32;
    int tx = threadIdx.x, ty = threadIdx.y;  // 32 x 8
    #pragma unroll
    for (int i = 0; i < 32; i += 8)
        tile[ty + i][tx] = W[(size_t)(k0 + ty + i) * N + n0 + tx];
    __syncthreads();
    #pragma unroll
    for (int i = 0; i < 32; i += 8)
        Th[(size_t)(n0 + ty + i) * K + k0 + tx] = __float2half_rn(tile[tx][ty + i]);
}

// ---------------- LayerNorm 1 -> fp16 ----------------------------------------
__global__ void ln1_kernel(const float* __restrict__ x,
                           const float* __restrict__ g,
                           const float* __restrict__ b,
                           __half* __restrict__ oh) {
    int row = blockIdx.x;
    float4 v = ((const float4*)(x + (size_t)row * CC))[threadIdx.x];
    float s = v.x + v.y + v.z + v.w;
    float q = v.x*v.x + v.y*v.y + v.z*v.z + v.w*v.w;
    int lane = threadIdx.x & 31, wid = threadIdx.x >> 5;
    #pragma unroll
    for (int o = 16; o; o >>= 1) {
        s += __shfl_xor_sync(0xffffffffu, s, o);
        q += __shfl_xor_sync(0xffffffffu, q, o);
    }
    __shared__ float s_s[8], s_q[8];
    if (!lane) { s_s[wid] = s; s_q[wid] = q; }
    __syncthreads();
    if (threadIdx.x == 0) {
        float a = 0.f, c2 = 0.f;
        #pragma unroll
        for (int i = 0; i < 8; i++) { a += s_s[i]; c2 += s_q[i]; }
        s_s[0] = a; s_q[0] = c2;
    }
    __syncthreads();
    float mean = s_s[0] * (1.0f / CC);
    float var  = s_q[0] * (1.0f / CC) - mean * mean;
    float rstd = rsqrtf(var + 1e-5f);
    float4 gv = ((const float4*)g)[threadIdx.x];
    float4 bv = ((const float4*)b)[threadIdx.x];
    __half2 h01 = __floats2half2_rn((v.x - mean) * rstd * gv.x + bv.x,
                                    (v.y - mean) * rstd * gv.y + bv.y);
    __half2 h23 = __floats2half2_rn((v.z - mean) * rstd * gv.z + bv.z,
                                    (v.w - mean) * rstd * gv.w + bv.w);
    __half2* ph = (__half2*)(oh + (size_t)row * CC);
    ph[threadIdx.x * 2] = h01;  ph[threadIdx.x * 2 + 1] = h23;
}

// ---------------- LayerNorm 2 + rr gate -> fp16 ------------------------------
__global__ void ln2_rr_kernel(const float* __restrict__ x1,
                              const float* __restrict__ g,
                              const float* __restrict__ b,
                              const float* __restrict__ cmr,
                              __half* __restrict__ oh,
                              float* __restrict__ rr) {
    int row = blockIdx.x;
    float4 v = ((const float4*)(x1 + (size_t)row * CC))[threadIdx.x];
    float s = v.x + v.y + v.z + v.w;
    float q = v.x*v.x + v.y*v.y + v.z*v.z + v.w*v.w;
    int lane = threadIdx.x & 31, wid = threadIdx.x >> 5;
    #pragma unroll
    for (int o = 16; o; o >>= 1) {
        s += __shfl_xor_sync(0xffffffffu, s, o);
        q += __shfl_xor_sync(0xffffffffu, q, o);
    }
    __shared__ float s_s[8], s_q[8];
    if (!lane) { s_s[wid] = s; s_q[wid] = q; }
    __syncthreads();
    if (threadIdx.x == 0) {
        float a = 0.f, c2 = 0.f;
        #pragma unroll
        for (int i = 0; i < 8; i++) { a += s_s[i]; c2 += s_q[i]; }
        s_s[0] = a; s_q[0] = c2;
    }
    __syncthreads();
    float mean = s_s[0] * (1.0f / CC);
    float var  = s_q[0] * (1.0f / CC) - mean * mean;
    float rstd = rsqrtf(var + 1e-5f);
    float4 gv = ((const float4*)g)[threadIdx.x];
    float4 bv = ((const float4*)b)[threadIdx.x];
    float o0 = (v.x - mean) * rstd * gv.x + bv.x;
    float o1 = (v.y - mean) * rstd * gv.y + bv.y;
    float o2 = (v.z - mean) * rstd * gv.z + bv.z;
    float o3 = (v.w - mean) * rstd * gv.w + bv.w;
    __half2* ph = (__half2*)(oh + (size_t)row * CC);
    ph[threadIdx.x * 2]     = __floats2half2_rn(o0, o1);
    ph[threadIdx.x * 2 + 1] = __floats2half2_rn(o2, o3);

    int t = row & (TT - 1);
    int prow = (t == 0) ? (row + TT - 1) : (row - 1);
    float4 xp = ((const float4*)(x1 + (size_t)prow * CC))[threadIdx.x];
    float4 cr = ((const float4*)cmr)[threadIdx.x];
    float4 r4;
    r4.x = sigmoidf_(xp.x + cr.x * (o0 - xp.x));
    r4.y = sigmoidf_(xp.y + cr.y * (o1 - xp.y));
    r4.z = sigmoidf_(xp.z + cr.z * (o2 - xp.z));
    r4.w = sigmoidf_(xp.w + cr.w * (o3 - xp.w));
    ((float4*)(rr + (size_t)row * CC))[threadIdx.x] = r4;
}

// ---------------- WKV scan (fused x1 = x + r*y) ------------------------------
#define PF 8
__global__ void wkv_kernel(const float* __restrict__ kvr,
                           const float* __restrict__ x,
                           const float* __restrict__ wd,
                           const float* __restrict__ uf,
                           float* __restrict__ x1,
                           float* __restrict__ out_state) {
    int gid = blockIdx.x * blockDim.x + threadIdx.x;
    int b = gid >> 10, c = gid & (CC - 1);
    float w = wd[c], u = uf[c];
    float aa = 0.0f, bb = -1e38f;
    size_t kbase = (size_t)b * TT * (3 * CC) + c;
    size_t xbase = (size_t)b * TT * CC + c;

    float pk[PF], pv[PF], pr[PF], px[PF];
    #pragma unroll
    for (int i = 0; i < PF; i++) {
        size_t ko = kbase + (size_t)i * (3 * CC);
        pk[i] = kvr[ko];  pv[i] = kvr[ko + CC];  pr[i] = kvr[ko + 2 * CC];
        px[i] = x[xbase + (size_t)i * CC];
    }
    for (int t0 = 0; t0 < TT; t0 += PF) {
        #pragma unroll
        for (int i = 0; i < PF; i++) {
            int t = t0 + i;
            float kk = pk[i], vv = pv[i], r = pr[i], xv = px[i];
            int tn = t + PF;
            if (tn < TT) {
                size_t ko = kbase + (size_t)tn * (3 * CC);
                pk[i] = kvr[ko];  pv[i] = kvr[ko + CC];  pr[i] = kvr[ko + 2 * CC];
                px[i] = x[xbase + (size_t)tn * CC];
            }
            float ww = u + kk;
            float p  = fmaxf(bb, ww);
            float e1 = __expf(bb - p);
            float e2 = __expf(ww - p);
            float y  = __fdividef(e1 * aa + e2 * vv, e1 + e2 + 1e-8f);
            x1[xbase + (size_t)t * CC] = xv + r * y;
            float w2 = w + bb;
            float p2 = fmaxf(w2, kk);
            float ea = __expf(w2 - p2);
            float eb = __expf(kk - p2);
            aa = ea * aa + eb * vv;
            bb = p2 + __logf(ea + eb + 1e-8f);
        }
    }
    out_state[(size_t)gid * 2 + 0] = aa;
    out_state[(size_t)gid * 2 + 1] = bb;
}

// ---------------- HMMA GEMM (G1/G2): C[128,256], warp 64x64 ------------------
// fp16 inputs, fp32 accumulate, cp.async 3-stage, cross-iteration frag pipeline.
// Single-barrier BK boundary: wait_group 0 -> BAR -> copy(ks+2) -> load k0 frags.
#define BKG 64
#define STAGES 3
#define STG_BYTES 49152            // A 128x64x2 = 16KB | B 256x64x2 = 32KB
#define GSMEM (STAGES * STG_BYTES)

template <int EPI>
__global__ void __launch_bounds__(256, 1)
mma_gemm(const __half* __restrict__ A, const __half* __restrict__ B,
         int K,
         float* __restrict__ outf, __half* __restrict__ outh,
         const float* __restrict__ e0, const float* __restrict__ e1,
         const float* __restrict__ e2, const float* __restrict__ e3) {
    extern __shared__ char smem[];
    const int tid = threadIdx.x;
    const int m0 = blockIdx.y * 128;
    const int n0 = blockIdx.x * 256;
    uint32_t sb = smem_u32(smem);
    const int warp = tid >> 5, lane = tid & 31;
    const int wm = warp >> 2, wn = warp & 3;   // warp tile: 64(m) x 64(n)

    float acc[4][8][4];
    #pragma unroll
    for (int i = 0; i < 4; i++)
        #pragma unroll
        for (int j = 0; j < 8; j++)
            #pragma unroll
            for (int e = 0; e < 4; e++) acc[i][j][e] = 0.f;

    const __half* Ab = A + (size_t)m0 * K;
    const __half* Bb = B + (size_t)n0 * K;
    const int crow = tid >> 3;            // 0..31
    const int ccol = tid & 7;             // 16B chunk 0..7

    auto copy_stage = [&](int ks, int buf) {
        int k0 = ks * BKG;
        uint32_t base = sb + (uint32_t)buf * STG_BYTES;
        #pragma unroll
        for (int i = 0; i < 4; i++) {     // A: 128 rows
            int row = i * 32 + crow;
            uint32_t sa = base + (uint32_t)row * 128 + (uint32_t)((ccol ^ (row & 7)) << 4);
            cp16(sa, Ab + (size_t)row * K + k0 + ccol * 8);
        }
        #pragma unroll
        for (int i = 0; i < 8; i++) {     // B: 256 rows
            int row = i * 32 + crow;
            uint32_t sa = base + 16384 + (uint32_t)row * 128 + (uint32_t)((ccol ^ (row & 7)) << 4);
            cp16(sa, Bb + (size_t)row * K + k0 + ccol * 8);
        }
        cp_commit();
    };

    copy_stage(0, 0);
    copy_stage(1, 1);

    const int lhalf = (lane >> 4) << 4;
    uint32_t a_base[4], a_sw[4], b_base[4], b_sw[4];
    #pragma unroll
    for (int mi = 0; mi < 4; mi++) {
        int row = wm * 64 + mi * 16 + (lane & 15);
        a_base[mi] = (uint32_t)row * 128;
        a_sw[mi]   = (uint32_t)((row & 7) << 4);
    }
    #pragma unroll
    for (int nq = 0; nq < 4; nq++) {
        int row = wn * 64 + nq * 16 + (lane & 15);
        b_base[nq] = 16384u + (uint32_t)row * 128;
        b_sw[nq]   = (uint32_t)((row & 7) << 4);
    }

    uint32_t afr[2][4][4];
    uint32_t bfr[2][4][4];

    auto load_frags = [&](uint32_t bufb, int kk, int fb) {
        uint32_t ch = (uint32_t)(kk * 32 + lhalf);
        #pragma unroll
        for (int mi = 0; mi < 4; mi++)
            ldx4(afr[fb][mi], bufb + a_base[mi] + (ch ^ a_sw[mi]));
        #pragma unroll
        for (int nq = 0; nq < 4; nq++)
            ldx4(bfr[fb][nq], bufb + b_base[nq] + (ch ^ b_sw[nq]));
    };
    auto do_mmas = [&](int fb) {
        #pragma unroll
        for (int mi = 0; mi < 4; mi++)
            #pragma unroll
            for (int nq = 0; nq < 4; nq++) {
                mma16816(acc[mi][2*nq+0], afr[fb][mi], bfr[fb][nq][0], bfr[fb][nq][2]);
                mma16816(acc[mi][2*nq+1], afr[fb][mi], bfr[fb][nq][1], bfr[fb][nq][3]);
            }
    };

    const int NK = K / BKG;
    asm volatile("cp.async.wait_group 1;" ::: "memory");
    __syncthreads();
    load_frags(sb, 0, 0);

    for (int ks = 0; ks < NK; ks++) {
        uint32_t bufb = sb + (uint32_t)(ks % STAGES) * STG_BYTES;
        #pragma unroll
        for (int kk = 0; kk < 4; kk++) {
            if (kk < 3) {
                load_frags(bufb, kk + 1, (kk + 1) & 1);
            } else if (ks + 1 < NK) {
                // Single-barrier boundary: stage ks+1 is the only outstanding
                // group; wait_group 0 completes it, the BAR publishes it and
                // simultaneously proves every warp is done reading the buffer
                // copy(ks+2) will overwrite.
                asm volatile("cp.async.wait_group 0;" ::: "memory");
                __syncthreads();
                if (ks + 2 < NK) copy_stage(ks + 2, (ks + 2) % STAGES);
                load_frags(sb + (uint32_t)((ks + 1) % STAGES) * STG_BYTES, 0, 0);
            }
            do_mmas(kk & 1);
        }
    }

    const int qr = lane >> 2;
    const int qe = lane & 3;
    #pragma unroll
    for (int mi = 0; mi < 4; mi++) {
        #pragma unroll
        for (int rh = 0; rh < 2; rh++) {
            int m = m0 + wm * 64 + mi * 16 + qr + rh * 8;
            int t = m & (TT - 1);
            if (EPI == 1) {
                int seg = n0 >> 10;
                const float* coefp = (seg == 0) ? e1 : (seg == 1) ? e2 : e3;
                int pm = t ? (m - 1) : m;
                const float* xpr = e0 + (size_t)pm * CC;
                float* orow = outf + (size_t)m * (3 * CC);
                #pragma unroll
                for (int nj = 0; nj < 8; nj++) {
                    int n = n0 + wn * 64 + nj * 8 + 2 * qe;
                    int c = n & (CC - 1);
                    float v0 = acc[mi][nj][rh * 2 + 0];
                    float v1 = acc[mi][nj][rh * 2 + 1];
                    float x0 = xpr[c], x1v = xpr[c + 1];
                    float a0 = x0  + coefp[c]     * (v0 - x0);
                    float a1 = x1v + coefp[c + 1] * (v1 - x1v);
                    if (seg == 2) { a0 = sigmoidf_(a0); a1 = sigmoidf_(a1); }
                    float2 o = {a0, a1};
                    *(float2*)(orow + n) = o;
                }
            } else {       // EPI == 2
                int pm = t ? (m - 1) : (m + TT - 1);
                const float* xpr = e0 + (size_t)pm * CC;
                size_t rowo = (size_t)m * (4 * CC);
                #pragma unroll
                for (int nj = 0; nj < 8; nj++) {
                    int n = n0 + wn * 64 + nj * 8 + 2 * qe;
                    int c = n & (CC - 1);
                    float v0 = acc[mi][nj][rh * 2 + 0];
                    float v1 = acc[mi][nj][rh * 2 + 1];
                    float x0 = xpr[c], x1v = xpr[c + 1];
                    float a0 = fmaxf(x0  + e1[c]     * (v0 - x0), 0.f);
                    float a1 = fmaxf(x1v + e1[c + 1] * (v1 - x1v), 0.f);
                    *(__half2*)(outh + rowo + n) = __floats2half2_rn(a0 * a0, a1 * a1);
                }
            }
        }
    }
}

// ---------------- HMMA GEMM3: C[128,128], warp 64x32 -------------------------
#define STG3_BYTES 32768           // A 128x64x2 = 16KB | B 128x64x2 = 16KB
#define G3SMEM (STAGES * STG3_BYTES)

__global__ void __launch_bounds__(256, 1)
mma_gemm3(const __half* __restrict__ A, const __half* __restrict__ B,
          int K, float* __restrict__ outf,
          const float* __restrict__ e0, const float* __restrict__ e1) {
    extern __shared__ char smem[];
    const int tid = threadIdx.x;
    const int m0 = blockIdx.y * 128;
    const int n0 = blockIdx.x * 128;
    uint32_t sb = smem_u32(smem);
    const int warp = tid >> 5, lane = tid & 31;
    const int wm = warp >> 2, wn = warp & 3;   // warp tile: 64(m) x 32(n)

    float acc[4][4][4];
    #pragma unroll
    for (int i = 0; i < 4; i++)
        #pragma unroll
        for (int j = 0; j < 4; j++)
            #pragma unroll
            for (int e = 0; e < 4; e++) acc[i][j][e] = 0.f;

    const __half* Ab = A + (size_t)m0 * K;
    const __half* Bb = B + (size_t)n0 * K;
    const int crow = tid >> 3;
    const int ccol = tid & 7;

    auto copy_stage = [&](int ks, int buf) {
        int k0 = ks * BKG;
        uint32_t base = sb + (uint32_t)buf * STG3_BYTES;
        #pragma unroll
        for (int i = 0; i < 4; i++) {     // A: 128 rows
            int row = i * 32 + crow;
            uint32_t sa = base + (uint32_t)row * 128 + (uint32_t)((ccol ^ (row & 7)) << 4);
            cp16(sa, Ab + (size_t)row * K + k0 + ccol * 8);
        }
        #pragma unroll
        for (int i = 0; i < 4; i++) {     // B: 128 rows
            int row = i * 32 + crow;
            uint32_t sa = base + 16384 + (uint32_t)row * 128 + (uint32_t)((ccol ^ (row & 7)) << 4);
            cp16(sa, Bb + (size_t)row * K + k0 + ccol * 8);
        }
        cp_commit();
    };

    copy_stage(0, 0);
    copy_stage(1, 1);

    const int lhalf = (lane >> 4) << 4;
    uint32_t a_base[4], a_sw[4], b_base[2], b_sw[2];
    #pragma unroll
    for (int mi = 0; mi < 4; mi++) {
        int row = wm * 64 + mi * 16 + (lane & 15);
        a_base[mi] = (uint32_t)row * 128;
        a_sw[mi]   = (uint32_t)((row & 7) << 4);
    }
    #pragma unroll
    for (int nq = 0; nq < 2; nq++) {
        int row = wn * 32 + nq * 16 + (lane & 15);
        b_base[nq] = 16384u + (uint32_t)row * 128;
        b_sw[nq]   = (uint32_t)((row & 7) << 4);
    }

    uint32_t afr[2][4][4];
    uint32_t bfr[2][2][4];

    auto load_frags = [&](uint32_t bufb, int kk, int fb) {
        uint32_t ch = (uint32_t)(kk * 32 + lhalf);
        #pragma unroll
        for (int mi = 0; mi < 4; mi++)
            ldx4(afr[fb][mi], bufb + a_base[mi] + (ch ^ a_sw[mi]));
        #pragma unroll
        for (int nq = 0; nq < 2; nq++)
            ldx4(bfr[fb][nq], bufb + b_base[nq] + (ch ^ b_sw[nq]));
    };
    auto do_mmas = [&](int fb) {
        #pragma unroll
        for (int mi = 0; mi < 4; mi++)
            #pragma unroll
            for (int nq = 0; nq < 2; nq++) {
                mma16816(acc[mi][2*nq+0], afr[fb][mi], bfr[fb][nq][0], bfr[fb][nq][2]);
                mma16816(acc[mi][2*nq+1], afr[fb][mi], bfr[fb][nq][1], bfr[fb][nq][3]);
            }
    };

    const int NK = K / BKG;
    asm volatile("cp.async.wait_group 1;" ::: "memory");
    __syncthreads();
    load_frags(sb, 0, 0);

    for (int ks = 0; ks < NK; ks++) {
        uint32_t bufb = sb + (uint32_t)(ks % STAGES) * STG3_BYTES;
        #pragma unroll
        for (int kk = 0; kk < 4; kk++) {
            if (kk < 3) {
                load_frags(bufb, kk + 1, (kk + 1) & 1);
            } else if (ks + 1 < NK) {
                asm volatile("cp.async.wait_group 0;" ::: "memory");
                __syncthreads();
                if (ks + 2 < NK) copy_stage(ks + 2, (ks + 2) % STAGES);
                load_frags(sb + (uint32_t)((ks + 1) % STAGES) * STG3_BYTES, 0, 0);
            }
            do_mmas(kk & 1);
        }
    }

    const int qr = lane >> 2;
    const int qe = lane & 3;
    #pragma unroll
    for (int mi = 0; mi < 4; mi++) {
        #pragma unroll
        for (int rh = 0; rh < 2; rh++) {
            int m = m0 + wm * 64 + mi * 16 + qr + rh * 8;
            size_t rowo = (size_t)m * CC;
            #pragma unroll
            for (int nj = 0; nj < 4; nj++) {
                int n = n0 + wn * 32 + nj * 8 + 2 * qe;
                float2 xv = *(const float2*)(e0 + rowo + n);
                float2 rv = *(const float2*)(e1 + rowo + n);
                float2 o;
                o.x = xv.x + rv.x * acc[mi][nj][rh * 2 + 0];
                o.y = xv.y + rv.y * acc[mi][nj][rh * 2 + 1];
                *(float2*)(outf + rowo + n) = o;
            }
        }
    }
}

// ---------------- launch ------------------------------------------------------
extern "C" void kernel_launch(void* const* d_in, const int* in_sizes, int n_in,
                              void* d_out, int out_size) {
    const float* x    = (const float*)d_in[0];
    const float* tdec = (const float*)d_in[1];
    const float* tfir = (const float*)d_in[2];
    const float* W_tm = (const float*)d_in[3];
    const float* g1   = (const float*)d_in[4];
    const float* b1   = (const float*)d_in[5];
    const float* tmk  = (const float*)d_in[6];
    const float* tmv  = (const float*)d_in[7];
    const float* tmr  = (const float*)d_in[8];
    const float* W_cm = (const float*)d_in[9];
    const float* W_cp = (const float*)d_in[10];
    const float* g2   = (const float*)d_in[11];
    const float* b2   = (const float*)d_in[12];
    const float* cmk  = (const float*)d_in[13];
    const float* cmr  = (const float*)d_in[14];
    float* out = (float*)d_out;

    float *kvr, *x1, *rr;
    __half *xn, *xn2, *hid, *wtm, *wcm, *wcp;
    cudaGetSymbolAddress((void**)&kvr, g_kvr);
    cudaGetSymbolAddress((void**)&x1,  g_x1);
    cudaGetSymbolAddress((void**)&rr,  g_rr);
    cudaGetSymbolAddress((void**)&xn,  g_xn);
    cudaGetSymbolAddress((void**)&xn2, g_xn2);
    cudaGetSymbolAddress((void**)&hid, g_hid);
    cudaGetSymbolAddress((void**)&wtm, g_wtm);
    cudaGetSymbolAddress((void**)&wcm, g_wcm);
    cudaGetSymbolAddress((void**)&wcp, g_wcp);

    cudaFuncSetAttribute(mma_gemm<1>, cudaFuncAttributeMaxDynamicSharedMemorySize, GSMEM);
    cudaFuncSetAttribute(mma_gemm<2>, cudaFuncAttributeMaxDynamicSharedMemorySize, GSMEM);
    cudaFuncSetAttribute(mma_gemm3,   cudaFuncAttributeMaxDynamicSharedMemorySize, G3SMEM);

    dim3 tb(32, 8);
    transpose_h<<<dim3(3*CC/32, CC/32), tb>>>(W_tm, wtm, CC, 3*CC);
    transpose_h<<<dim3(4*CC/32, CC/32), tb>>>(W_cm, wcm, CC, 4*CC);
    transpose_h<<<dim3(CC/32, 4*CC/32), tb>>>(W_cp, wcp, 4*CC, CC);

    // 1) LN1 -> fp16
    ln1_kernel<<<MM, 256>>>(x, g1, b1, xn);
    // 2) GEMM1 + time-mix epilogue -> kvr (fp32)
    mma_gemm<1><<<dim3(3*CC/256, MM/128), 256, GSMEM>>>(
        xn, wtm, CC, kvr, nullptr, x, tmk, tmv, tmr);
    // 3) WKV scan -> x1, state tail of out
    wkv_kernel<<<(BB*CC)/64, 64>>>(kvr, x, tdec, tfir, x1, out + (size_t)MM * CC);
    // 4) LN2 + rr gate -> fp16 + rr
    ln2_rr_kernel<<<MM, 256>>>(x1, g2, b2, cmr, xn2, rr);
    // 5) GEMM2 + channel-mix relu^2 epilogue -> hidden fp16
    mma_gemm<2><<<dim3(4*CC/256, MM/128), 256, GSMEM>>>(
        xn2, wcm, CC, nullptr, hid, x1, cmk, nullptr, nullptr);
    // 6) GEMM3 (128x128 tiles) + final epilogue -> out = x1 + rr*vv
    mma_gemm3<<<dim3(CC/128, MM/128), 256, G3SMEM>>>(
        hid, wcp, 4*CC, out, x1, rr);
}